// round 9
// baseline (speedup 1.0000x reference)
#include <cuda_runtime.h>
#include <cstdint>

// ---------------------------------------------------------------------------
// FeatureIntegration: gather+pad -> SE gate -> GEMM (32768x1536 @ 1536x256)
// Round 9: byte-identical resubmit of R8 (container flake, never compiled;
// same playbook as R5->R6 which passed unchanged). Single-sync pipelined
// GEMM: A path (LDG+gate+cvt+STS) after compute into the other AS buffer;
// B via 3-buffer cp.async ring; gates read from L2 (no GS); grid (2,256) so
// col-half pairs share x through L2. Fragment math identical to R6/R7.
// ---------------------------------------------------------------------------

#define N_ENT    32
#define C_DIM    64
#define OUT_DIM  256
#define LEN_M    16
#define LEN_L    8
#define B_SZ     1024
#define ROWS_TOT (B_SZ * N_ENT)     // 32768

#define KT_TILES 48                 // 48 K-tiles of 32 floats = K_eff 1536
#define PITCH    36                 // AS row pitch (floats)

// smem float offsets
#define SM_AS0 0                    // 128*36 = 4608
#define SM_AS1 4608
#define SM_BS  9216                 // 3 x 128*32 = 3*4096
#define SM_FLOATS 21504             // 86016 bytes

__device__ float g_gate[(size_t)ROWS_TOT * C_DIM];          // 8.4 MB
__device__ float g_wt[2 * KT_TILES * 128 * 32];             // 1.5 MB tile images

__device__ __forceinline__ uint32_t f2tf32(float f) {
    uint32_t r;
    asm("cvt.rna.tf32.f32 %0, %1;" : "=r"(r) : "f"(f));
    return r;
}

__device__ __forceinline__ uint32_t smem_u32(const void* p) {
    uint32_t a;
    asm("{ .reg .u64 t; cvta.to.shared.u64 t, %1; cvt.u32.u64 %0, t; }"
        : "=r"(a) : "l"(p));
    return a;
}

__device__ __forceinline__ void cp16(uint32_t dst, const void* src) {
    asm volatile("cp.async.cg.shared.global [%0], [%1], 16;"
                 :: "r"(dst), "l"(src) : "memory");
}
#define CP_COMMIT() asm volatile("cp.async.commit_group;" ::: "memory")
#define CP_WAIT(N)  asm volatile("cp.async.wait_group %0;" :: "n"(N) : "memory")

__device__ __forceinline__ void mma_tf32(float* d, const uint32_t* a, const uint32_t* b) {
    asm volatile(
        "mma.sync.aligned.m16n8k8.row.col.f32.tf32.tf32.f32 "
        "{%0,%1,%2,%3}, {%4,%5,%6,%7}, {%8,%9}, {%0,%1,%2,%3};"
        : "+f"(d[0]), "+f"(d[1]), "+f"(d[2]), "+f"(d[3])
        : "r"(a[0]), "r"(a[1]), "r"(a[2]), "r"(a[3]), "r"(b[0]), "r"(b[1]));
}

// ---------------------------------------------------------------------------
// Kernel 1: SE gate (unchanged; measured 36us @ 70% DRAM).
// ---------------------------------------------------------------------------
__global__ __launch_bounds__(256)
void gate_kernel(const float* __restrict__ xm,
                 const float* __restrict__ xl,
                 const float* __restrict__ w1,
                 const float* __restrict__ w2)
{
    const int tid = threadIdx.x;
    const int grp = tid >> 4;
    const int j   = tid & 15;
    const int bn  = blockIdx.x * 16 + grp;
    const int b   = bn >> 5;
    const int n   = bn & 31;

    const float4* pm = (const float4*)(xm
        + ((size_t)(b * (N_ENT * LEN_M) + n * LEN_M)) * C_DIM) + j;
    float4 s = make_float4(0.f, 0.f, 0.f, 0.f);
#pragma unroll
    for (int t = 0; t < LEN_M; t++) {
        float4 v = pm[t * 16];
        s.x += v.x; s.y += v.y; s.z += v.z; s.w += v.w;
    }
    const float4* pl = (const float4*)(xl
        + ((size_t)(b * (N_ENT * LEN_L) + n * LEN_L)) * C_DIM) + j;
#pragma unroll
    for (int t = 0; t < LEN_L; t++) {
        float4 v = pl[t * 16];
        s.x += v.x; s.y += v.y; s.z += v.z; s.w += v.w;
    }
    const float inv = 1.0f / 32.0f;
    s.x *= inv; s.y *= inv; s.z *= inv; s.w *= inv;

    float h[4];
#pragma unroll
    for (int i = 0; i < 4; i++) {
        float4 w = *(const float4*)(w1 + i * C_DIM + j * 4);
        h[i] = s.x * w.x + s.y * w.y + s.z * w.z + s.w * w.w;
    }
#pragma unroll
    for (int off = 8; off; off >>= 1)
#pragma unroll
        for (int i = 0; i < 4; i++)
            h[i] += __shfl_xor_sync(0xFFFFFFFFu, h[i], off);
#pragma unroll
    for (int i = 0; i < 4; i++) h[i] = fmaxf(h[i], 0.f);

    float4 g4;
#pragma unroll
    for (int q = 0; q < 4; q++) {
        int c = j * 4 + q;
        float4 w = *(const float4*)(w2 + c * 4);
        float z = h[0] * w.x + h[1] * w.y + h[2] * w.z + h[3] * w.w;
        ((float*)&g4)[q] = 1.0f / (1.0f + __expf(-z));
    }
    *(float4*)(g_gate + (size_t)bn * C_DIM + j * 4) = g4;
}

// ---------------------------------------------------------------------------
// Kernel 2: W prep (unchanged): permuted + XOR-swizzled tf32 tile images.
// ---------------------------------------------------------------------------
__global__ __launch_bounds__(256)
void wprep_kernel(const float* __restrict__ aw)
{
    int gi = blockIdx.x * 256 + threadIdx.x;
    int qp = gi & 7;
    int n  = (gi >> 3) & 127;
    int hk = gi >> 10;
    int kt = hk % 48;
    int h  = hk / 48;
    int o  = h * 128 + n;
    int q  = qp ^ (n & 7);

    float4 v;
#pragma unroll
    for (int e = 0; e < 4; e++) {
        int pk = q * 4 + e;
        int k  = ((pk & 7) << 2) | (pk >> 3);
        int f  = kt * 32 + k + (kt >= 32 ? 256 : 0);
        ((float*)&v)[e] = __uint_as_float(f2tf32(aw[(size_t)o * 2048 + f]));
    }
    ((float4*)g_wt)[gi] = v;
}

// ---------------------------------------------------------------------------
// A-tile store: tile ktn into AS buffer dst (gate LDG from L2, cvt, permuted STS).
// ---------------------------------------------------------------------------
__device__ __forceinline__ void store_a_tile(float* dst, int ktn, int row_base,
                                             int tid,
                                             const float* __restrict__ xm,
                                             const float* __restrict__ xl)
{
    const int t  = ktn >> 1;
    const int c0 = (ktn & 1) * 32;
#pragma unroll
    for (int i = 0; i < 8; i++) {
        int lin = i * 128 + tid;
        int r = lin >> 3, c4 = lin & 7;
        int bn = row_base + r, b = bn >> 5, n = bn & 31;
        const float* src = (t < LEN_M)
            ? xm + (((size_t)(b * (N_ENT * LEN_M) + n * LEN_M + t)) * C_DIM + c0 + c4 * 4)
            : xl + (((size_t)(b * (N_ENT * LEN_L) + n * LEN_L + (t - LEN_M))) * C_DIM + c0 + c4 * 4);
        float4 v = *(const float4*)src;
        float4 g = *(const float4*)&g_gate[(size_t)bn * C_DIM + c0 + c4 * 4];
        float* ap = dst + r * PITCH + c4;
        ap[0]  = __uint_as_float(f2tf32(v.x * g.x));
        ap[8]  = __uint_as_float(f2tf32(v.y * g.y));
        ap[16] = __uint_as_float(f2tf32(v.z * g.z));
        ap[24] = __uint_as_float(f2tf32(v.w * g.w));
    }
}

// ---------------------------------------------------------------------------
// Kernel 3: single-sync pipelined mma.sync tf32 GEMM. CTA 128x128, 4 warps.
// grid = (2 col-halves, 256 row-blocks) so the two halves of a row-block are
// adjacent block IDs (x re-read hits L2).
// ---------------------------------------------------------------------------
__global__ __launch_bounds__(128, 2)
void gemm_mma(const float* __restrict__ xm,
              const float* __restrict__ xl,
              const float* __restrict__ bias,
              float* __restrict__ out)
{
    extern __shared__ float sm[];
    const uint32_t sb = smem_u32(sm);

    const int tid  = threadIdx.x;
    const int lane = tid & 31;
    const int wid  = tid >> 5;
    const int tig  = lane & 3;
    const int grp  = lane >> 2;
    const int wrow = (wid >> 1) * 64;
    const int wcol = (wid & 1) * 64;
    const int h        = blockIdx.x;              // col half
    const int row_base = blockIdx.y * 128;
    const int col_base = h * 128;

    const float4* wt_base = (const float4*)g_wt + (size_t)h * KT_TILES * 1024;

    // prologue: B0, B1 via cp.async; A0 store; wait B0; sync
#pragma unroll
    for (int st = 0; st < 2; st++) {
        const float4* src = wt_base + (size_t)st * 1024;
        uint32_t dst = sb + (SM_BS + st * 4096) * 4;
#pragma unroll
        for (int i = 0; i < 8; i++) {
            int gi = i * 128 + tid;
            cp16(dst + gi * 16, src + gi);
        }
        CP_COMMIT();
    }
    store_a_tile(sm + SM_AS0, 0, row_base, tid, xm, xl);

    float acc[4][8][4];
#pragma unroll
    for (int mt = 0; mt < 4; mt++)
#pragma unroll
        for (int nt = 0; nt < 8; nt++)
#pragma unroll
            for (int q = 0; q < 4; q++) acc[mt][nt][q] = 0.f;

    CP_WAIT(1);
    __syncthreads();

    for (int kt = 0; kt < KT_TILES; kt++) {
        const float* AS = sm + ((kt & 1) ? SM_AS1 : SM_AS0);
        const float* BS = sm + SM_BS + (kt % 3) * 4096;

        // ---- compute (fragment math identical to R6/R7) ----
#pragma unroll
        for (int ph = 0; ph < 2; ph++) {
            uint32_t af[4][8];
#pragma unroll
            for (int mt = 0; mt < 4; mt++) {
                int r = wrow + mt * 16 + grp;
                *(uint4*)&af[mt][0] = *(const uint4*)&AS[r * PITCH + tig * 8 + ph * 4];
                *(uint4*)&af[mt][4] = *(const uint4*)&AS[(r + 8) * PITCH + tig * 8 + ph * 4];
            }
            uint32_t bf[8][4];
#pragma unroll
            for (int nt = 0; nt < 8; nt++) {
                int n = wcol + nt * 8 + grp;
                int qp = ((tig * 2 + ph) ^ (n & 7)) * 4;
                *(uint4*)&bf[nt][0] = *(const uint4*)&BS[n * 32 + qp];
            }
#pragma unroll
            for (int s = 0; s < 2; s++) {
#pragma unroll
                for (int mt = 0; mt < 4; mt++) {
                    uint32_t a[4] = { af[mt][s * 2], af[mt][4 + s * 2],
                                      af[mt][1 + s * 2], af[mt][5 + s * 2] };
#pragma unroll
                    for (int nt = 0; nt < 8; nt++) {
                        uint32_t b[2] = { bf[nt][s * 2], bf[nt][s * 2 + 1] };
                        mma_tf32(acc[mt][nt], a, b);
                    }
                }
            }
        }

        // ---- overlap region: A(kt+1) into the other AS buffer; B(kt+2) cp ----
        if (kt + 1 < KT_TILES)
            store_a_tile(sm + ((kt & 1) ? SM_AS0 : SM_AS1), kt + 1,
                         row_base, tid, xm, xl);
        if (kt + 2 < KT_TILES) {
            const float4* src = wt_base + (size_t)(kt + 2) * 1024;
            uint32_t dst = sb + (SM_BS + ((kt + 2) % 3) * 4096) * 4;
#pragma unroll
            for (int i = 0; i < 8; i++) {
                int gi = i * 128 + tid;
                cp16(dst + gi * 16, src + gi);
            }
            CP_COMMIT();
            CP_WAIT(1);       // B(kt+1) landed
        } else {
            CP_WAIT(0);
        }
        __syncthreads();
    }

    // ---- epilogue ----
#pragma unroll
    for (int mt = 0; mt < 4; mt++) {
        int gr = row_base + wrow + mt * 16 + grp;
#pragma unroll
        for (int nt = 0; nt < 8; nt++) {
            int gc = col_base + wcol + nt * 8 + tig * 2;
            float2 bb = *(const float2*)&bias[gc];
            float2 v0; v0.x = acc[mt][nt][0] + bb.x; v0.y = acc[mt][nt][1] + bb.y;
            *(float2*)&out[(size_t)gr * OUT_DIM + gc] = v0;
            float2 v1; v1.x = acc[mt][nt][2] + bb.x; v1.y = acc[mt][nt][3] + bb.y;
            *(float2*)&out[(size_t)(gr + 8) * OUT_DIM + gc] = v1;
        }
    }
}

// ---------------------------------------------------------------------------
// Launch. Inputs: x_metric, x_log, y(unused), se_w1, se_w2, align_w, align_b.
// ---------------------------------------------------------------------------
extern "C" void kernel_launch(void* const* d_in, const int* in_sizes, int n_in,
                              void* d_out, int out_size)
{
    const float* xm = (const float*)d_in[0];
    const float* xl = (const float*)d_in[1];
    const float* w1 = (const float*)d_in[3];
    const float* w2 = (const float*)d_in[4];
    const float* aw = (const float*)d_in[5];
    const float* ab = (const float*)d_in[6];
    float* out = (float*)d_out;

    const int smem_bytes = SM_FLOATS * (int)sizeof(float);   // 86016
    cudaFuncSetAttribute(gemm_mma, cudaFuncAttributeMaxDynamicSharedMemorySize, smem_bytes);

    gate_kernel<<<ROWS_TOT / 16, 256>>>(xm, xl, w1, w2);
    wprep_kernel<<<(2 * KT_TILES * 128 * 8) / 256, 256>>>(aw);
    dim3 grid(2, ROWS_TOT / 128);
    gemm_mma<<<grid, 128, smem_bytes>>>(xm, xl, ab, out);
}

// round 12
// speedup vs baseline: 2.0731x; 2.0731x over previous
#include <cuda_runtime.h>
#include <cuda_fp16.h>
#include <cstdint>

// ---------------------------------------------------------------------------
// FeatureIntegration: gather+pad -> SE gate -> GEMM (32768x1536 @ 1536x256)
// Round 12: third submit of the R10 fp16 kernel (two consecutive container
// flakes; fragment algebra independently re-derived and verified this round).
// R7's PROVEN skeleton (prefetch-A-regs -> storeA -> compute, 2 syncs, gates
// in smem, double-buffered cp.async B) with fp16 m16n8k16 MMA (same 10-bit
// mantissa as tf32, half the MMA count).
// ---------------------------------------------------------------------------

#define N_ENT    32
#define C_DIM    64
#define OUT_DIM  256
#define LEN_M    16
#define LEN_L    8
#define B_SZ     1024
#define ROWS_TOT (B_SZ * N_ENT)     // 32768

#define KT_TILES 48                 // 48 K-tiles of 32 floats = K_eff 1536

// smem u32 offsets
#define SM_AS  0                    // 128 rows x 16 half2-units = 2048
#define SM_BS0 2048
#define SM_BS1 4096
#define SM_GS  6144                 // gates: 128 x 64 f32 = 8192
#define SM_U32 14336                // 57344 bytes

__device__ float    g_gate[(size_t)ROWS_TOT * C_DIM];   // 8.4 MB
__device__ unsigned g_wt[2 * KT_TILES * 128 * 16];      // fp16 swizzled tiles

__device__ __forceinline__ uint32_t smem_u32(const void* p) {
    uint32_t a;
    asm("{ .reg .u64 t; cvta.to.shared.u64 t, %1; cvt.u32.u64 %0, t; }"
        : "=r"(a) : "l"(p));
    return a;
}

__device__ __forceinline__ void cp16(uint32_t dst, const void* src) {
    asm volatile("cp.async.cg.shared.global [%0], [%1], 16;"
                 :: "r"(dst), "l"(src) : "memory");
}
#define CP_COMMIT() asm volatile("cp.async.commit_group;" ::: "memory")
#define CP_WAIT(N)  asm volatile("cp.async.wait_group %0;" :: "n"(N) : "memory")

__device__ __forceinline__ uint32_t pack2(float lo, float hi) {
    __half2 h = __floats2half2_rn(lo, hi);   // .x = lo (lower k), .y = hi
    return *(uint32_t*)&h;
}

__device__ __forceinline__ void mma_f16(float* d, const uint32_t* a, const uint32_t* b) {
    asm volatile(
        "mma.sync.aligned.m16n8k16.row.col.f32.f16.f16.f32 "
        "{%0,%1,%2,%3}, {%4,%5,%6,%7}, {%8,%9}, {%0,%1,%2,%3};"
        : "+f"(d[0]), "+f"(d[1]), "+f"(d[2]), "+f"(d[3])
        : "r"(a[0]), "r"(a[1]), "r"(a[2]), "r"(a[3]), "r"(b[0]), "r"(b[1]));
}

// ---------------------------------------------------------------------------
// Kernel 1: SE gate (unchanged; 36us @ 70% DRAM).
// ---------------------------------------------------------------------------
__global__ __launch_bounds__(256)
void gate_kernel(const float* __restrict__ xm,
                 const float* __restrict__ xl,
                 const float* __restrict__ w1,
                 const float* __restrict__ w2)
{
    const int tid = threadIdx.x;
    const int grp = tid >> 4;
    const int j   = tid & 15;
    const int bn  = blockIdx.x * 16 + grp;
    const int b   = bn >> 5;
    const int n   = bn & 31;

    const float4* pm = (const float4*)(xm
        + ((size_t)(b * (N_ENT * LEN_M) + n * LEN_M)) * C_DIM) + j;
    float4 s = make_float4(0.f, 0.f, 0.f, 0.f);
#pragma unroll
    for (int t = 0; t < LEN_M; t++) {
        float4 v = pm[t * 16];
        s.x += v.x; s.y += v.y; s.z += v.z; s.w += v.w;
    }
    const float4* pl = (const float4*)(xl
        + ((size_t)(b * (N_ENT * LEN_L) + n * LEN_L)) * C_DIM) + j;
#pragma unroll
    for (int t = 0; t < LEN_L; t++) {
        float4 v = pl[t * 16];
        s.x += v.x; s.y += v.y; s.z += v.z; s.w += v.w;
    }
    const float inv = 1.0f / 32.0f;
    s.x *= inv; s.y *= inv; s.z *= inv; s.w *= inv;

    float h[4];
#pragma unroll
    for (int i = 0; i < 4; i++) {
        float4 w = *(const float4*)(w1 + i * C_DIM + j * 4);
        h[i] = s.x * w.x + s.y * w.y + s.z * w.z + s.w * w.w;
    }
#pragma unroll
    for (int off = 8; off; off >>= 1)
#pragma unroll
        for (int i = 0; i < 4; i++)
            h[i] += __shfl_xor_sync(0xFFFFFFFFu, h[i], off);
#pragma unroll
    for (int i = 0; i < 4; i++) h[i] = fmaxf(h[i], 0.f);

    float4 g4;
#pragma unroll
    for (int q = 0; q < 4; q++) {
        int c = j * 4 + q;
        float4 w = *(const float4*)(w2 + c * 4);
        float z = h[0] * w.x + h[1] * w.y + h[2] * w.z + h[3] * w.w;
        ((float*)&g4)[q] = 1.0f / (1.0f + __expf(-z));
    }
    *(float4*)(g_gate + (size_t)bn * C_DIM + j * 4) = g4;
}

// ---------------------------------------------------------------------------
// Kernel 2: W prep -> fp16 swizzled tile images.
// Row n of tile (h,kt): 16 half2 units (unit u = k 2u,2u+1), stored at
// logical pos p(u)=4*(u&3)+(u>>2), granule-XOR g^=((n>>1)&3).
// One thread = one 16B granule (4 units).
// ---------------------------------------------------------------------------
__global__ __launch_bounds__(256)
void wprep_kernel(const float* __restrict__ aw)
{
    int gid = blockIdx.x * 256 + threadIdx.x;     // 49152 granules
    int gp  = gid & 3;
    int n   = (gid >> 2) & 127;
    int hk  = gid >> 9;                           // h*48 + kt
    int kt  = hk % 48;
    int h   = hk / 48;
    int o   = h * 128 + n;
    int gl  = gp ^ ((n >> 1) & 3);

    uint4 v;
#pragma unroll
    for (int j = 0; j < 4; j++) {
        int u = 4 * j + gl;                       // unit at logical pos gl*4+j
        int f = kt * 32 + 2 * u + (kt >= 32 ? 256 : 0);
        ((uint32_t*)&v)[j] = pack2(aw[(size_t)o * 2048 + f],
                                   aw[(size_t)o * 2048 + f + 1]);
    }
    ((uint4*)g_wt)[gid] = v;
}

// ---------------------------------------------------------------------------
// Kernel 3: pipelined mma.sync fp16 GEMM. CTA 128x128, 4 warps (64x64),
// structure identical to R7 (the 241us kernel).
// ---------------------------------------------------------------------------
__global__ __launch_bounds__(128, 2)
void gemm_mma(const float* __restrict__ xm,
              const float* __restrict__ xl,
              const float* __restrict__ bias,
              float* __restrict__ out)
{
    extern __shared__ uint32_t smu[];
    uint32_t* AS = smu + SM_AS;
    float*    GS = (float*)(smu + SM_GS);
    const uint32_t sb = smem_u32(smu);

    const int tid  = threadIdx.x;
    const int lane = tid & 31;
    const int wid  = tid >> 5;
    const int tig  = lane & 3;
    const int grp  = lane >> 2;
    const int wrow = (wid >> 1) * 64;
    const int wcol = (wid & 1) * 64;
    const int row_base = blockIdx.x * 128;
    const int h        = blockIdx.y;              // col half
    const int col_base = h * 128;

    // gate preload (128 rows x 64 f32)
    {
        const float4* gsrc = (const float4*)(g_gate + (size_t)row_base * C_DIM);
        float4* gdst = (float4*)GS;
#pragma unroll
        for (int i = 0; i < 16; i++) gdst[i * 128 + tid] = gsrc[i * 128 + tid];
    }

    // B tile 0 via cp.async (512 granules)
    const uint4* wt_base = (const uint4*)g_wt + (size_t)h * KT_TILES * 512;
    {
        uint32_t dst = sb + SM_BS0 * 4;
#pragma unroll
        for (int i = 0; i < 4; i++) {
            int gi = i * 128 + tid;
            cp16(dst + gi * 16, wt_base + gi);
        }
        CP_COMMIT();
    }

    // A tile 0 prefetch into registers
    float4 va[8];
    {
#pragma unroll
        for (int i = 0; i < 8; i++) {
            int lin = i * 128 + tid;
            int r = lin >> 3, c4 = lin & 7;
            int bn = row_base + r, b = bn >> 5, n = bn & 31;
            va[i] = *(const float4*)(xm
                + (((size_t)(b * (N_ENT * LEN_M) + n * LEN_M + 0)) * C_DIM + c4 * 4));
        }
    }

    float acc[4][8][4];
#pragma unroll
    for (int mt = 0; mt < 4; mt++)
#pragma unroll
        for (int nt = 0; nt < 8; nt++)
#pragma unroll
            for (int q = 0; q < 4; q++) acc[mt][nt][q] = 0.f;

    __syncthreads();   // GS ready

    for (int kt = 0; kt < KT_TILES; kt++) {
        const int cur = kt & 1;
        const int c0  = (kt & 1) * 32;

        // ---- store A tile: gate, cvt fp16, permuted+swizzled STS ----
#pragma unroll
        for (int i = 0; i < 8; i++) {
            int lin = i * 128 + tid;
            int r = lin >> 3, c4 = lin & 7;
            float4 v = va[i];
            float4 g = *(const float4*)&GS[r * C_DIM + c0 + c4 * 4];
            uint32_t u0 = pack2(v.x * g.x, v.y * g.y);   // k = 4c4, 4c4+1
            uint32_t u1 = pack2(v.z * g.z, v.w * g.w);   // k = 4c4+2, 4c4+3
            int xr  = (r >> 1) & 3;
            int q0  = (2 * c4) & 3;                      // 0 or 2
            int off = c4 >> 1;
            AS[r * 16 + (((q0    ) ^ xr) << 2) + off] = u0;
            AS[r * 16 + (((q0 | 1) ^ xr) << 2) + off] = u1;
        }
        // ---- cp.async B tile kt+1 into the other buffer ----
        if (kt + 1 < KT_TILES) {
            const uint4* src = wt_base + (size_t)(kt + 1) * 512;
            uint32_t dst = sb + (cur ? SM_BS0 : SM_BS1) * 4;
#pragma unroll
            for (int i = 0; i < 4; i++) {
                int gi = i * 128 + tid;
                cp16(dst + gi * 16, src + gi);
            }
            CP_COMMIT();
            CP_WAIT(1);     // B(kt) landed
        } else {
            CP_WAIT(0);
        }
        __syncthreads();

        // ---- prefetch A tile kt+1 into registers (overlaps MMA) ----
        if (kt + 1 < KT_TILES) {
            const int t2 = (kt + 1) >> 1, c02 = ((kt + 1) & 1) * 32;
#pragma unroll
            for (int i = 0; i < 8; i++) {
                int lin = i * 128 + tid;
                int r = lin >> 3, c4 = lin & 7;
                int bn = row_base + r, b = bn >> 5, n = bn & 31;
                const float* src = (t2 < LEN_M)
                    ? xm + (((size_t)(b * (N_ENT * LEN_M) + n * LEN_M + t2)) * C_DIM + c02 + c4 * 4)
                    : xl + (((size_t)(b * (N_ENT * LEN_L) + n * LEN_L + (t2 - LEN_M))) * C_DIM + c02 + c4 * 4);
                va[i] = *(const float4*)src;
            }
        }

        // ---- compute: fragments via single LDS.128 each, 64 MMAs/warp ----
        const uint32_t* BS = smu + (cur ? SM_BS1 : SM_BS0);
        uint32_t afA[4][4], afB[4][4];
#pragma unroll
        for (int mt = 0; mt < 4; mt++) {
            int r = wrow + mt * 16 + grp;
            int pg = (tig ^ ((r >> 1) & 3)) * 4;
            *(uint4*)&afA[mt][0] = *(const uint4*)&AS[r * 16 + pg];
            *(uint4*)&afB[mt][0] = *(const uint4*)&AS[(r + 8) * 16 + pg];
        }
        uint32_t bf[8][4];
#pragma unroll
        for (int nt = 0; nt < 8; nt++) {
            int n = wcol + nt * 8 + grp;
            int pg = (tig ^ ((n >> 1) & 3)) * 4;
            *(uint4*)&bf[nt][0] = *(const uint4*)&BS[n * 16 + pg];
        }
#pragma unroll
        for (int s = 0; s < 2; s++) {
#pragma unroll
            for (int mt = 0; mt < 4; mt++) {
                uint32_t a[4] = { afA[mt][2 * s], afB[mt][2 * s],
                                  afA[mt][2 * s + 1], afB[mt][2 * s + 1] };
#pragma unroll
                for (int nt = 0; nt < 8; nt++) {
                    uint32_t b[2] = { bf[nt][2 * s], bf[nt][2 * s + 1] };
                    mma_f16(acc[mt][nt], a, b);
                }
            }
        }
        __syncthreads();
    }

    // ---- epilogue (same d-fragment mapping as tf32) ----
#pragma unroll
    for (int mt = 0; mt < 4; mt++) {
        int gr = row_base + wrow + mt * 16 + grp;
#pragma unroll
        for (int nt = 0; nt < 8; nt++) {
            int gc = col_base + wcol + nt * 8 + tig * 2;
            float2 bb = *(const float2*)&bias[gc];
            float2 v0; v0.x = acc[mt][nt][0] + bb.x; v0.y = acc[mt][nt][1] + bb.y;
            *(float2*)&out[(size_t)gr * OUT_DIM + gc] = v0;
            float2 v1; v1.x = acc[mt][nt][2] + bb.x; v1.y = acc[mt][nt][3] + bb.y;
            *(float2*)&out[(size_t)(gr + 8) * OUT_DIM + gc] = v1;
        }
    }
}

// ---------------------------------------------------------------------------
// Launch. Inputs: x_metric, x_log, y(unused), se_w1, se_w2, align_w, align_b.
// ---------------------------------------------------------------------------
extern "C" void kernel_launch(void* const* d_in, const int* in_sizes, int n_in,
                              void* d_out, int out_size)
{
    const float* xm = (const float*)d_in[0];
    const float* xl = (const float*)d_in[1];
    const float* w1 = (const float*)d_in[3];
    const float* w2 = (const float*)d_in[4];
    const float* aw = (const float*)d_in[5];
    const float* ab = (const float*)d_in[6];
    float* out = (float*)d_out;

    const int smem_bytes = SM_U32 * 4;   // 57344
    cudaFuncSetAttribute(gemm_mma, cudaFuncAttributeMaxDynamicSharedMemorySize, smem_bytes);

    gate_kernel<<<ROWS_TOT / 16, 256>>>(xm, xl, w1, w2);
    wprep_kernel<<<(2 * KT_TILES * 128 * 4) / 256, 256>>>(aw);
    dim3 grid(ROWS_TOT / 128, OUT_DIM / 128);
    gemm_mma<<<grid, 128, smem_bytes>>>(xm, xl, ab, out);
}

// round 14
// speedup vs baseline: 2.6021x; 1.2551x over previous
#include <cuda_runtime.h>
#include <cuda_fp16.h>
#include <cstdint>

// ---------------------------------------------------------------------------
// FeatureIntegration: gather+pad -> SE gate -> GEMM (32768x1536 @ 1536x256)
// Round 14: byte-identical resubmit of R13 (container flake; playbook from
// R5->R6, R10->R12). A-path moved out of the GEMM entirely:
//  - gatea_kernel: loads each row's 24 t-positions once (kept in regs),
//    computes the SE gate, emits gated fp16 fragment-permuted XOR-swizzled
//    A tile images to g_a (same layout math R12 verified in-kernel).
//  - gemm: pure cp.async streaming of A+B images, 3-stage ring, ONE
//    __syncthreads per tile, inner loop = 8 cp + 16 LDS.128 + 64 HMMA.
// ---------------------------------------------------------------------------

#define N_ENT    32
#define C_DIM    64
#define OUT_DIM  256
#define LEN_M    16
#define LEN_L    8
#define B_SZ     1024
#define ROWS_TOT (B_SZ * N_ENT)     // 32768

#define KT_TILES 48                 // 48 K-tiles of 32 floats = K_eff 1536

// smem u32 offsets: 3 stages x (A 2048 + B 2048)
#define SM_STAGE 4096
#define SM_U32   12288              // 49152 bytes

__device__ unsigned g_a[(size_t)256 * KT_TILES * 2048];     // 100.7 MB A images
__device__ unsigned g_wt[2 * KT_TILES * 128 * 16];          // 786 KB B images

__device__ __forceinline__ uint32_t smem_u32(const void* p) {
    uint32_t a;
    asm("{ .reg .u64 t; cvta.to.shared.u64 t, %1; cvt.u32.u64 %0, t; }"
        : "=r"(a) : "l"(p));
    return a;
}

__device__ __forceinline__ void cp16(uint32_t dst, const void* src) {
    asm volatile("cp.async.cg.shared.global [%0], [%1], 16;"
                 :: "r"(dst), "l"(src) : "memory");
}
#define CP_COMMIT() asm volatile("cp.async.commit_group;" ::: "memory")
#define CP_WAIT(N)  asm volatile("cp.async.wait_group %0;" :: "n"(N) : "memory")

__device__ __forceinline__ uint32_t pack2(float lo, float hi) {
    __half2 h = __floats2half2_rn(lo, hi);   // .x = lo (lower k), .y = hi
    return *(uint32_t*)&h;
}

__device__ __forceinline__ void mma_f16(float* d, const uint32_t* a, const uint32_t* b) {
    asm volatile(
        "mma.sync.aligned.m16n8k16.row.col.f32.f16.f16.f32 "
        "{%0,%1,%2,%3}, {%4,%5,%6,%7}, {%8,%9}, {%0,%1,%2,%3};"
        : "+f"(d[0]), "+f"(d[1]), "+f"(d[2]), "+f"(d[3])
        : "r"(a[0]), "r"(a[1]), "r"(a[2]), "r"(a[3]), "r"(b[0]), "r"(b[1]));
}

// ---------------------------------------------------------------------------
// Kernel 1: fused SE gate + A-image emit.
// 16 threads per (b,n); thread j owns channels 4j..4j+3. All 24 t-positions
// loaded once into registers (pooling reuses them), then gated, packed fp16,
// and scattered to g_a with the R12-verified permute+swizzle formula.
// ---------------------------------------------------------------------------
__global__ __launch_bounds__(128)
void gatea_kernel(const float* __restrict__ xm,
                  const float* __restrict__ xl,
                  const float* __restrict__ w1,   // (4,64)
                  const float* __restrict__ w2)   // (64,4)
{
    const int tid = threadIdx.x;
    const int j   = tid & 15;
    const int bn  = blockIdx.x * 8 + (tid >> 4);
    const int b   = bn >> 5;
    const int n   = bn & 31;

    // load all 24 t-positions for this thread's channel quad
    float4 xv[24];
    const float4* pm = (const float4*)(xm
        + ((size_t)(b * (N_ENT * LEN_M) + n * LEN_M)) * C_DIM) + j;
#pragma unroll
    for (int t = 0; t < LEN_M; t++) xv[t] = pm[t * 16];
    const float4* pl = (const float4*)(xl
        + ((size_t)(b * (N_ENT * LEN_L) + n * LEN_L)) * C_DIM) + j;
#pragma unroll
    for (int t = 0; t < LEN_L; t++) xv[LEN_M + t] = pl[t * 16];

    // pooled mean
    float4 s = make_float4(0.f, 0.f, 0.f, 0.f);
#pragma unroll
    for (int t = 0; t < 24; t++) {
        s.x += xv[t].x; s.y += xv[t].y; s.z += xv[t].z; s.w += xv[t].w;
    }
    const float inv = 1.0f / 32.0f;
    s.x *= inv; s.y *= inv; s.z *= inv; s.w *= inv;

    // SE squeeze: h = relu(pooled @ w1^T) via 16-lane shuffle reduce
    float h[4];
#pragma unroll
    for (int i = 0; i < 4; i++) {
        float4 w = *(const float4*)(w1 + i * C_DIM + j * 4);
        h[i] = s.x * w.x + s.y * w.y + s.z * w.z + s.w * w.w;
    }
#pragma unroll
    for (int off = 8; off; off >>= 1)
#pragma unroll
        for (int i = 0; i < 4; i++)
            h[i] += __shfl_xor_sync(0xFFFFFFFFu, h[i], off);
#pragma unroll
    for (int i = 0; i < 4; i++) h[i] = fmaxf(h[i], 0.f);

    // excite: gate = sigmoid(h @ w2^T) for this thread's 4 channels
    float4 g4;
#pragma unroll
    for (int q = 0; q < 4; q++) {
        int c = j * 4 + q;
        float4 w = *(const float4*)(w2 + c * 4);
        float z = h[0] * w.x + h[1] * w.y + h[2] * w.z + h[3] * w.w;
        ((float*)&g4)[q] = 1.0f / (1.0f + __expf(-z));
    }

    // emit gated fp16 A tile images (permute+swizzle identical to R12 store)
    const int r   = bn & 127;
    const int rb  = bn >> 7;
    const int xr  = (r >> 1) & 3;
    const int c4  = j & 7;
    const int q0  = (2 * c4) & 3;
    const int off = c4 >> 1;
    const int a0  = ((q0      ^ xr) << 2) + off;
    const int a1  = (((q0 | 1) ^ xr) << 2) + off;
    const int ktb = j >> 3;                       // which 32-ch half of t
#pragma unroll
    for (int t = 0; t < 24; t++) {
        unsigned* base = g_a + ((size_t)(rb * KT_TILES + 2 * t + ktb)) * 2048 + r * 16;
        float4 v = xv[t];
        base[a0] = pack2(v.x * g4.x, v.y * g4.y);
        base[a1] = pack2(v.z * g4.z, v.w * g4.w);
    }
}

// ---------------------------------------------------------------------------
// Kernel 2: W prep -> fp16 swizzled tile images (unchanged from R12).
// ---------------------------------------------------------------------------
__global__ __launch_bounds__(256)
void wprep_kernel(const float* __restrict__ aw)
{
    int gid = blockIdx.x * 256 + threadIdx.x;     // 49152 granules
    int gp  = gid & 3;
    int n   = (gid >> 2) & 127;
    int hk  = gid >> 9;                           // h*48 + kt
    int kt  = hk % 48;
    int h   = hk / 48;
    int o   = h * 128 + n;
    int gl  = gp ^ ((n >> 1) & 3);

    uint4 v;
#pragma unroll
    for (int j = 0; j < 4; j++) {
        int u = 4 * j + gl;
        int f = kt * 32 + 2 * u + (kt >= 32 ? 256 : 0);
        ((uint32_t*)&v)[j] = pack2(aw[(size_t)o * 2048 + f],
                                   aw[(size_t)o * 2048 + f + 1]);
    }
    ((uint4*)g_wt)[gid] = v;
}

// ---------------------------------------------------------------------------
// Kernel 3: pure-streaming fp16 GEMM. CTA 128x128, 4 warps (64x64).
// 3-stage cp.async ring for A+B, ONE sync per tile. Fragment math = R12.
// ---------------------------------------------------------------------------
__global__ __launch_bounds__(128, 2)
void gemm_mma(const float* __restrict__ bias,
              float* __restrict__ out)
{
    extern __shared__ uint32_t smu[];
    const uint32_t sb = smem_u32(smu);

    const int tid  = threadIdx.x;
    const int lane = tid & 31;
    const int wid  = tid >> 5;
    const int tig  = lane & 3;
    const int grp  = lane >> 2;
    const int wrow = (wid >> 1) * 64;
    const int wcol = (wid & 1) * 64;
    const int rb       = blockIdx.x;              // row block
    const int row_base = rb * 128;
    const int h        = blockIdx.y;              // col half
    const int col_base = h * 128;

    const uint4* a_base  = (const uint4*)(g_a  + (size_t)rb * KT_TILES * 2048);
    const uint4* b_base  = (const uint4*)g_wt + (size_t)h * KT_TILES * 512;

    // issue one tile's A+B copies into stage st
    auto cp_tile = [&](int kt, int st) {
        uint32_t dst = sb + (st * SM_STAGE) * 4;
        const uint4* sa = a_base + (size_t)kt * 512;
        const uint4* sbp = b_base + (size_t)kt * 512;
#pragma unroll
        for (int i = 0; i < 4; i++) {
            int gi = i * 128 + tid;
            cp16(dst + gi * 16, sa + gi);
        }
#pragma unroll
        for (int i = 0; i < 4; i++) {
            int gi = i * 128 + tid;
            cp16(dst + 8192 + gi * 16, sbp + gi);
        }
    };

    // prologue: tiles 0,1 in flight; wait tile0; sync
    cp_tile(0, 0); CP_COMMIT();
    cp_tile(1, 1); CP_COMMIT();

    float acc[4][8][4];
#pragma unroll
    for (int mt = 0; mt < 4; mt++)
#pragma unroll
        for (int nt = 0; nt < 8; nt++)
#pragma unroll
            for (int q = 0; q < 4; q++) acc[mt][nt][q] = 0.f;

    CP_WAIT(1);
    __syncthreads();

    for (int kt = 0; kt < KT_TILES; kt++) {
        const int st = kt % 3;
        // prefetch tile kt+2 (stage last read at kt-1, safe per end-sync)
        if (kt + 2 < KT_TILES) {
            cp_tile(kt + 2, (kt + 2) % 3);
            CP_COMMIT();
        }

        // fragment loads from stage st (group kt done+visible by invariant)
        const uint32_t* AS = smu + st * SM_STAGE;
        const uint32_t* BS = AS + 2048;
        uint32_t afA[4][4], afB[4][4];
#pragma unroll
        for (int mt = 0; mt < 4; mt++) {
            int r = wrow + mt * 16 + grp;
            int pg = (tig ^ ((r >> 1) & 3)) * 4;
            *(uint4*)&afA[mt][0] = *(const uint4*)&AS[r * 16 + pg];
            *(uint4*)&afB[mt][0] = *(const uint4*)&AS[(r + 8) * 16 + pg];
        }
        uint32_t bf[8][4];
#pragma unroll
        for (int nt = 0; nt < 8; nt++) {
            int n = wcol + nt * 8 + grp;
            int pg = (tig ^ ((n >> 1) & 3)) * 4;
            *(uint4*)&bf[nt][0] = *(const uint4*)&BS[n * 16 + pg];
        }
#pragma unroll
        for (int s = 0; s < 2; s++) {
#pragma unroll
            for (int mt = 0; mt < 4; mt++) {
                uint32_t a[4] = { afA[mt][2 * s], afB[mt][2 * s],
                                  afA[mt][2 * s + 1], afB[mt][2 * s + 1] };
#pragma unroll
                for (int nt = 0; nt < 8; nt++) {
                    uint32_t b[2] = { bf[nt][2 * s], bf[nt][2 * s + 1] };
                    mma_f16(acc[mt][nt], a, b);
                }
            }
        }

        // establish tile kt+1 for next iteration, free stage st for kt+3
        if (kt + 2 < KT_TILES) { CP_WAIT(1); } else { CP_WAIT(0); }
        __syncthreads();
    }

    // epilogue
#pragma unroll
    for (int mt = 0; mt < 4; mt++) {
        int gr = row_base + wrow + mt * 16 + grp;
#pragma unroll
        for (int nt = 0; nt < 8; nt++) {
            int gc = col_base + wcol + nt * 8 + tig * 2;
            float2 bb = *(const float2*)&bias[gc];
            float2 v0; v0.x = acc[mt][nt][0] + bb.x; v0.y = acc[mt][nt][1] + bb.y;
            *(float2*)&out[(size_t)gr * OUT_DIM + gc] = v0;
            float2 v1; v1.x = acc[mt][nt][2] + bb.x; v1.y = acc[mt][nt][3] + bb.y;
            *(float2*)&out[(size_t)(gr + 8) * OUT_DIM + gc] = v1;
        }
    }
}

// ---------------------------------------------------------------------------
// Launch. Inputs: x_metric, x_log, y(unused), se_w1, se_w2, align_w, align_b.
// ---------------------------------------------------------------------------
extern "C" void kernel_launch(void* const* d_in, const int* in_sizes, int n_in,
                              void* d_out, int out_size)
{
    const float* xm = (const float*)d_in[0];
    const float* xl = (const float*)d_in[1];
    const float* w1 = (const float*)d_in[3];
    const float* w2 = (const float*)d_in[4];
    const float* aw = (const float*)d_in[5];
    const float* ab = (const float*)d_in[6];
    float* out = (float*)d_out;

    const int smem_bytes = SM_U32 * 4;   // 49152
    cudaFuncSetAttribute(gemm_mma, cudaFuncAttributeMaxDynamicSharedMemorySize, smem_bytes);

    gatea_kernel<<<ROWS_TOT / 8, 128>>>(xm, xl, w1, w2);
    wprep_kernel<<<(2 * KT_TILES * 128 * 4) / 256, 256>>>(aw);
    dim3 grid(ROWS_TOT / 128, OUT_DIM / 128);
    gemm_mma<<<grid, 128, smem_bytes>>>(ab, out);
}

// round 15
// speedup vs baseline: 2.6928x; 1.0349x over previous
#include <cuda_runtime.h>
#include <cuda_fp16.h>
#include <cstdint>

// ---------------------------------------------------------------------------
// FeatureIntegration: gather+pad -> SE gate -> GEMM (32768x1536 @ 1536x256)
// Round 15: R14 (138.7us) + K-tile merge in the GEMM. gatea/wprep untouched
// (gatea measured at DRAM roofline). GEMM now processes K=64 per iteration:
// 24 iterations, ONE sync each, 128 HMMAs between syncs, 3-stage cp.async
// ring of 32KB stages (A16K+B16K, both contiguous in the prebuilt images).
// Fragment/swizzle math byte-identical to the R12-verified code.
// ---------------------------------------------------------------------------

#define N_ENT    32
#define C_DIM    64
#define OUT_DIM  256
#define LEN_M    16
#define LEN_L    8
#define B_SZ     1024
#define ROWS_TOT (B_SZ * N_ENT)     // 32768

#define KT_TILES 48                 // K32 image tiles (storage layout)
#define TT       24                 // K64 compute iterations

// smem u32 offsets: 3 stages x (A 4096 + B 4096)
#define SM_STAGE 8192
#define SM_U32   24576              // 98304 bytes

__device__ unsigned g_a[(size_t)256 * KT_TILES * 2048];     // 100.7 MB A images
__device__ unsigned g_wt[2 * KT_TILES * 128 * 16];          // 786 KB B images

__device__ __forceinline__ uint32_t smem_u32(const void* p) {
    uint32_t a;
    asm("{ .reg .u64 t; cvta.to.shared.u64 t, %1; cvt.u32.u64 %0, t; }"
        : "=r"(a) : "l"(p));
    return a;
}

__device__ __forceinline__ void cp16(uint32_t dst, const void* src) {
    asm volatile("cp.async.cg.shared.global [%0], [%1], 16;"
                 :: "r"(dst), "l"(src) : "memory");
}
#define CP_COMMIT() asm volatile("cp.async.commit_group;" ::: "memory")
#define CP_WAIT(N)  asm volatile("cp.async.wait_group %0;" :: "n"(N) : "memory")

__device__ __forceinline__ uint32_t pack2(float lo, float hi) {
    __half2 h = __floats2half2_rn(lo, hi);   // .x = lo (lower k), .y = hi
    return *(uint32_t*)&h;
}

__device__ __forceinline__ void mma_f16(float* d, const uint32_t* a, const uint32_t* b) {
    asm volatile(
        "mma.sync.aligned.m16n8k16.row.col.f32.f16.f16.f32 "
        "{%0,%1,%2,%3}, {%4,%5,%6,%7}, {%8,%9}, {%0,%1,%2,%3};"
        : "+f"(d[0]), "+f"(d[1]), "+f"(d[2]), "+f"(d[3])
        : "r"(a[0]), "r"(a[1]), "r"(a[2]), "r"(a[3]), "r"(b[0]), "r"(b[1]));
}

// ---------------------------------------------------------------------------
// Kernel 1: fused SE gate + A-image emit (byte-identical to R14; at roofline).
// ---------------------------------------------------------------------------
__global__ __launch_bounds__(128)
void gatea_kernel(const float* __restrict__ xm,
                  const float* __restrict__ xl,
                  const float* __restrict__ w1,   // (4,64)
                  const float* __restrict__ w2)   // (64,4)
{
    const int tid = threadIdx.x;
    const int j   = tid & 15;
    const int bn  = blockIdx.x * 8 + (tid >> 4);
    const int b   = bn >> 5;
    const int n   = bn & 31;

    float4 xv[24];
    const float4* pm = (const float4*)(xm
        + ((size_t)(b * (N_ENT * LEN_M) + n * LEN_M)) * C_DIM) + j;
#pragma unroll
    for (int t = 0; t < LEN_M; t++) xv[t] = pm[t * 16];
    const float4* pl = (const float4*)(xl
        + ((size_t)(b * (N_ENT * LEN_L) + n * LEN_L)) * C_DIM) + j;
#pragma unroll
    for (int t = 0; t < LEN_L; t++) xv[LEN_M + t] = pl[t * 16];

    float4 s = make_float4(0.f, 0.f, 0.f, 0.f);
#pragma unroll
    for (int t = 0; t < 24; t++) {
        s.x += xv[t].x; s.y += xv[t].y; s.z += xv[t].z; s.w += xv[t].w;
    }
    const float inv = 1.0f / 32.0f;
    s.x *= inv; s.y *= inv; s.z *= inv; s.w *= inv;

    float h[4];
#pragma unroll
    for (int i = 0; i < 4; i++) {
        float4 w = *(const float4*)(w1 + i * C_DIM + j * 4);
        h[i] = s.x * w.x + s.y * w.y + s.z * w.z + s.w * w.w;
    }
#pragma unroll
    for (int off = 8; off; off >>= 1)
#pragma unroll
        for (int i = 0; i < 4; i++)
            h[i] += __shfl_xor_sync(0xFFFFFFFFu, h[i], off);
#pragma unroll
    for (int i = 0; i < 4; i++) h[i] = fmaxf(h[i], 0.f);

    float4 g4;
#pragma unroll
    for (int q = 0; q < 4; q++) {
        int c = j * 4 + q;
        float4 w = *(const float4*)(w2 + c * 4);
        float z = h[0] * w.x + h[1] * w.y + h[2] * w.z + h[3] * w.w;
        ((float*)&g4)[q] = 1.0f / (1.0f + __expf(-z));
    }

    const int r   = bn & 127;
    const int rb  = bn >> 7;
    const int xr  = (r >> 1) & 3;
    const int c4  = j & 7;
    const int q0  = (2 * c4) & 3;
    const int off = c4 >> 1;
    const int a0  = ((q0      ^ xr) << 2) + off;
    const int a1  = (((q0 | 1) ^ xr) << 2) + off;
    const int ktb = j >> 3;
#pragma unroll
    for (int t = 0; t < 24; t++) {
        unsigned* base = g_a + ((size_t)(rb * KT_TILES + 2 * t + ktb)) * 2048 + r * 16;
        float4 v = xv[t];
        base[a0] = pack2(v.x * g4.x, v.y * g4.y);
        base[a1] = pack2(v.z * g4.z, v.w * g4.w);
    }
}

// ---------------------------------------------------------------------------
// Kernel 2: W prep -> fp16 swizzled tile images (unchanged from R12/R14).
// ---------------------------------------------------------------------------
__global__ __launch_bounds__(256)
void wprep_kernel(const float* __restrict__ aw)
{
    int gid = blockIdx.x * 256 + threadIdx.x;     // 49152 granules
    int gp  = gid & 3;
    int n   = (gid >> 2) & 127;
    int hk  = gid >> 9;                           // h*48 + kt
    int kt  = hk % 48;
    int h   = hk / 48;
    int o   = h * 128 + n;
    int gl  = gp ^ ((n >> 1) & 3);

    uint4 v;
#pragma unroll
    for (int j = 0; j < 4; j++) {
        int u = 4 * j + gl;
        int f = kt * 32 + 2 * u + (kt >= 32 ? 256 : 0);
        ((uint32_t*)&v)[j] = pack2(aw[(size_t)o * 2048 + f],
                                   aw[(size_t)o * 2048 + f + 1]);
    }
    ((uint4*)g_wt)[gid] = v;
}

// ---------------------------------------------------------------------------
// Kernel 3: streaming fp16 GEMM, K-tile 64. CTA 128x128, 4 warps (64x64).
// 3-stage ring of 32KB stages (A 16KB | B 16KB), one sync per iteration.
// ---------------------------------------------------------------------------
__global__ __launch_bounds__(128, 2)
void gemm_mma(const float* __restrict__ bias,
              float* __restrict__ out)
{
    extern __shared__ uint32_t smu[];
    const uint32_t sb = smem_u32(smu);

    const int tid  = threadIdx.x;
    const int lane = tid & 31;
    const int wid  = tid >> 5;
    const int tig  = lane & 3;
    const int grp  = lane >> 2;
    const int wrow = (wid >> 1) * 64;
    const int wcol = (wid & 1) * 64;
    const int rb       = blockIdx.x;              // row block
    const int row_base = rb * 128;
    const int h        = blockIdx.y;              // col half
    const int col_base = h * 128;

    const uint4* a_base = (const uint4*)(g_a + (size_t)rb * KT_TILES * 2048);
    const uint4* b_base = (const uint4*)g_wt + (size_t)h * KT_TILES * 512;

    // one K64 tile = 16KB A + 16KB B, both contiguous (two K32 images)
    auto cp_tile = [&](int tt, int st) {
        uint32_t dst = sb + (st * SM_STAGE) * 4;
        const uint4* sa  = a_base + (size_t)tt * 1024;
        const uint4* sbp = b_base + (size_t)tt * 1024;
#pragma unroll
        for (int i = 0; i < 8; i++) {
            int gi = i * 128 + tid;
            cp16(dst + gi * 16, sa + gi);
        }
#pragma unroll
        for (int i = 0; i < 8; i++) {
            int gi = i * 128 + tid;
            cp16(dst + 16384 + gi * 16, sbp + gi);
        }
    };

    // prologue: tiles 0,1 in flight; establish tile 0
    cp_tile(0, 0); CP_COMMIT();
    cp_tile(1, 1); CP_COMMIT();

    float acc[4][8][4];
#pragma unroll
    for (int mt = 0; mt < 4; mt++)
#pragma unroll
        for (int nt = 0; nt < 8; nt++)
#pragma unroll
            for (int q = 0; q < 4; q++) acc[mt][nt][q] = 0.f;

    CP_WAIT(1);
    __syncthreads();

    for (int tt = 0; tt < TT; tt++) {
        const int st = tt % 3;
        if (tt + 2 < TT) {
            cp_tile(tt + 2, (tt + 2) % 3);
            CP_COMMIT();
        }

        // two K32 sub-tiles, fragment math identical to R12
#pragma unroll
        for (int sub = 0; sub < 2; sub++) {
            const uint32_t* AS = smu + st * SM_STAGE + sub * 2048;
            const uint32_t* BS = smu + st * SM_STAGE + 4096 + sub * 2048;
            uint32_t afA[4][4], afB[4][4];
#pragma unroll
            for (int mt = 0; mt < 4; mt++) {
                int r = wrow + mt * 16 + grp;
                int pg = (tig ^ ((r >> 1) & 3)) * 4;
                *(uint4*)&afA[mt][0] = *(const uint4*)&AS[r * 16 + pg];
                *(uint4*)&afB[mt][0] = *(const uint4*)&AS[(r + 8) * 16 + pg];
            }
            uint32_t bf[8][4];
#pragma unroll
            for (int nt = 0; nt < 8; nt++) {
                int n = wcol + nt * 8 + grp;
                int pg = (tig ^ ((n >> 1) & 3)) * 4;
                *(uint4*)&bf[nt][0] = *(const uint4*)&BS[n * 16 + pg];
            }
#pragma unroll
            for (int s = 0; s < 2; s++) {
#pragma unroll
                for (int mt = 0; mt < 4; mt++) {
                    uint32_t a[4] = { afA[mt][2 * s], afB[mt][2 * s],
                                      afA[mt][2 * s + 1], afB[mt][2 * s + 1] };
#pragma unroll
                    for (int nt = 0; nt < 8; nt++) {
                        uint32_t b[2] = { bf[nt][2 * s], bf[nt][2 * s + 1] };
                        mma_f16(acc[mt][nt], a, b);
                    }
                }
            }
        }

        if (tt + 2 < TT) { CP_WAIT(1); } else { CP_WAIT(0); }
        __syncthreads();
    }

    // epilogue
#pragma unroll
    for (int mt = 0; mt < 4; mt++) {
        int gr = row_base + wrow + mt * 16 + grp;
#pragma unroll
        for (int nt = 0; nt < 8; nt++) {
            int gc = col_base + wcol + nt * 8 + tig * 2;
            float2 bb = *(const float2*)&bias[gc];
            float2 v0; v0.x = acc[mt][nt][0] + bb.x; v0.y = acc[mt][nt][1] + bb.y;
            *(float2*)&out[(size_t)gr * OUT_DIM + gc] = v0;
            float2 v1; v1.x = acc[mt][nt][2] + bb.x; v1.y = acc[mt][nt][3] + bb.y;
            *(float2*)&out[(size_t)(gr + 8) * OUT_DIM + gc] = v1;
        }
    }
}

// ---------------------------------------------------------------------------
// Launch. Inputs: x_metric, x_log, y(unused), se_w1, se_w2, align_w, align_b.
// ---------------------------------------------------------------------------
extern "C" void kernel_launch(void* const* d_in, const int* in_sizes, int n_in,
                              void* d_out, int out_size)
{
    const float* xm = (const float*)d_in[0];
    const float* xl = (const float*)d_in[1];
    const float* w1 = (const float*)d_in[3];
    const float* w2 = (const float*)d_in[4];
    const float* aw = (const float*)d_in[5];
    const float* ab = (const float*)d_in[6];
    float* out = (float*)d_out;

    const int smem_bytes = SM_U32 * 4;   // 98304
    cudaFuncSetAttribute(gemm_mma, cudaFuncAttributeMaxDynamicSharedMemorySize, smem_bytes);

    gatea_kernel<<<ROWS_TOT / 8, 128>>>(xm, xl, w1, w2);
    wprep_kernel<<<(2 * KT_TILES * 128 * 4) / 256, 256>>>(aw);
    dim3 grid(ROWS_TOT / 128, OUT_DIM / 128);
    gemm_mma<<<grid, 128, smem_bytes>>>(ab, out);
}